// round 7
// baseline (speedup 1.0000x reference)
#include <cuda_runtime.h>
#include <cstdint>
#include <math.h>

// Problem constants
//  B=4, L=1024, E=1024, H=16, D=64, HID=1024, R=4
//  output: concat(out [4,1024,1024], w [4,1024,1024,16]) as float32

// ---------------------------------------------------------------------------
// Scratch (static device arrays; no allocations allowed)
// g_Q / g_Kb / g_TV hold tf32-rounded bit patterns (consumed only by MMAs).
// ---------------------------------------------------------------------------
__device__ float g_Q[4u * 16u * 1024u * 64u];      // [b][h][i][d]   (tf32 bits)
__device__ float g_Kb[4u * 16u * 1024u * 64u];     // [b][h][j][d]   (tf32 bits)
__device__ float g_TV[4u * 16u * 1024u * 64u];     // tanh(v)        (tf32 bits)
__device__ float g_SG[4u * 1024u * 16u * 64u];     // sigmoid(g) [b][i][h*64+d]
__device__ float g_gated[4u * 1024u * 1024u];      // [b][i][hd]
__device__ int   g_kpm_mode;                       // 0=32-bit word, 1=u8, 2=u16

// ---------------------------------------------------------------------------
// Helpers
// ---------------------------------------------------------------------------
__device__ __forceinline__ uint32_t f2tf(float x) {
    uint32_t r;
    asm("cvt.rna.tf32.f32 %0, %1;" : "=r"(r) : "f"(x));
    return r;
}

__device__ __forceinline__ void mma_tf32(float (&d)[4], const uint32_t (&a)[4],
                                         const uint32_t (&b)[2]) {
    asm volatile(
        "mma.sync.aligned.m16n8k8.row.col.f32.tf32.tf32.f32 "
        "{%0,%1,%2,%3}, {%4,%5,%6,%7}, {%8,%9}, {%0,%1,%2,%3};\n"
        : "+f"(d[0]), "+f"(d[1]), "+f"(d[2]), "+f"(d[3])
        : "r"(a[0]), "r"(a[1]), "r"(a[2]), "r"(a[3]), "r"(b[0]), "r"(b[1]));
}

__device__ __forceinline__ void cp_async16(uint32_t dst_smem, const void* src) {
    asm volatile("cp.async.cg.shared.global [%0], [%1], 16;\n"
                 :: "r"(dst_smem), "l"(src));
}
__device__ __forceinline__ void cp_async_commit() {
    asm volatile("cp.async.commit_group;\n" ::: "memory");
}
__device__ __forceinline__ void cp_async_wait0() {
    asm volatile("cp.async.wait_group 0;\n" ::: "memory");
}

// ---------------------------------------------------------------------------
// key_padding_mask dtype probe
// ---------------------------------------------------------------------------
__global__ void detect_kpm_kernel(const unsigned int* __restrict__ kpm) {
    __shared__ int s_f32, s_bf16, s_u8;
    if (threadIdx.x == 0) { s_f32 = 0; s_bf16 = 0; s_u8 = 0; }
    __syncthreads();
    for (int i = threadIdx.x; i < 1024; i += blockDim.x) {
        unsigned int w = kpm[i];
        if (w == 0x3F800000u) atomicOr(&s_f32, 1);
        else if ((w & 0xFFFFu) == 0x3F80u || (w >> 16) == 0x3F80u) atomicOr(&s_bf16, 1);
        else if (w > 1u) atomicOr(&s_u8, 1);
    }
    __syncthreads();
    if (threadIdx.x == 0) {
        int mode = 0;
        if (s_bf16) mode = 2;
        else if (s_f32) mode = 0;
        else if (s_u8) mode = 1;
        g_kpm_mode = mode;
    }
}

// ---------------------------------------------------------------------------
// tf32 GEMM: C[m,n] = sum_k A[m,k] * B[n,k], 128x128x32 tiles
//   mode 0: A=query, B=proj_w, epilogue splits QKVG (Q/K/tanhV as tf32 bits)
//   mode 2: A=g_gated, B=out_w, C=d_out + out_b
// ---------------------------------------------------------------------------
__global__ __launch_bounds__(256, 1)
void gemm_tf32_kernel(int mode, const float* __restrict__ Aext,
                      const float* __restrict__ Bext,
                      const float* __restrict__ bias, float* __restrict__ Cext) {
    __shared__ uint32_t As[128][36];
    __shared__ uint32_t Bs[128][36];

    const int tid = threadIdx.x;
    const int warp = tid >> 5, lane = tid & 31;
    const int wm = warp >> 1, wn = warp & 1;
    const int r = lane >> 2, c = lane & 3;

    const float* Ap; const float* Bp;
    if (mode == 2) { Ap = g_gated; Bp = Bext; }
    else           { Ap = Aext;    Bp = Bext; }
    const int m0 = blockIdx.y * 128;
    const int n0 = blockIdx.x * 128;

    float acc[2][8][4];
#pragma unroll
    for (int mt = 0; mt < 2; ++mt)
#pragma unroll
        for (int nt = 0; nt < 8; ++nt)
#pragma unroll
            for (int e = 0; e < 4; ++e) acc[mt][nt][e] = 0.f;

    const int kv4 = (tid & 7) * 4;
    const int rb = tid >> 3;

    float4 pa[4], pb[4];
    auto load_tile = [&](int kb) {
#pragma unroll
        for (int q = 0; q < 4; ++q) {
            int row = rb + q * 32;
            pa[q] = *reinterpret_cast<const float4*>(Ap + (size_t)(m0 + row) * 1024 + kb * 32 + kv4);
            pb[q] = *reinterpret_cast<const float4*>(Bp + (size_t)(n0 + row) * 1024 + kb * 32 + kv4);
        }
    };
    auto store_tile = [&]() {
#pragma unroll
        for (int q = 0; q < 4; ++q) {
            int row = rb + q * 32;
            As[row][kv4 + 0] = f2tf(pa[q].x); As[row][kv4 + 1] = f2tf(pa[q].y);
            As[row][kv4 + 2] = f2tf(pa[q].z); As[row][kv4 + 3] = f2tf(pa[q].w);
            Bs[row][kv4 + 0] = f2tf(pb[q].x); Bs[row][kv4 + 1] = f2tf(pb[q].y);
            Bs[row][kv4 + 2] = f2tf(pb[q].z); Bs[row][kv4 + 3] = f2tf(pb[q].w);
        }
    };

    const int nk = 32;  // K=1024
    load_tile(0);
    store_tile();
    __syncthreads();

    for (int kb = 0; kb < nk; ++kb) {
        if (kb + 1 < nk) load_tile(kb + 1);
#pragma unroll
        for (int ks = 0; ks < 4; ++ks) {
            const int kk = ks * 8;
            uint32_t af[2][4], bf[8][2];
#pragma unroll
            for (int mt = 0; mt < 2; ++mt) {
                int row0 = wm * 32 + mt * 16 + r;
                af[mt][0] = As[row0][kk + c];
                af[mt][1] = As[row0 + 8][kk + c];
                af[mt][2] = As[row0][kk + c + 4];
                af[mt][3] = As[row0 + 8][kk + c + 4];
            }
#pragma unroll
            for (int nt = 0; nt < 8; ++nt) {
                int col0 = wn * 64 + nt * 8 + r;
                bf[nt][0] = Bs[col0][kk + c];
                bf[nt][1] = Bs[col0][kk + c + 4];
            }
#pragma unroll
            for (int mt = 0; mt < 2; ++mt)
#pragma unroll
                for (int nt = 0; nt < 8; ++nt)
                    mma_tf32(acc[mt][nt], af[mt], bf[nt]);
        }
        __syncthreads();
        if (kb + 1 < nk) { store_tile(); __syncthreads(); }
    }

#pragma unroll
    for (int mt = 0; mt < 2; ++mt)
#pragma unroll
        for (int nt = 0; nt < 8; ++nt)
#pragma unroll
            for (int e = 0; e < 4; ++e) {
                int row = m0 + wm * 32 + mt * 16 + r + ((e >> 1) << 3);
                int col = n0 + wn * 64 + nt * 8 + 2 * c + (e & 1);
                float v = acc[mt][nt][e];
                if (mode == 0) {
                    v += bias[col];
                    int sec = col >> 10, cc = col & 1023;
                    int h = cc >> 6, d = cc & 63;
                    int b = row >> 10, i = row & 1023;
                    size_t hidx = (((size_t)b * 16 + h) * 1024 + i) * 64 + d;
                    if (sec == 0) g_Q[hidx] = __uint_as_float(f2tf(v));
                    else if (sec == 1) g_Kb[hidx] = __uint_as_float(f2tf(v));
                    else if (sec == 2) g_TV[hidx] = __uint_as_float(f2tf(tanhf(v)));
                    else g_SG[((size_t)(b * 1024 + i) * 16 + h) * 64 + d] =
                             1.0f / (1.0f + __expf(-v));
                } else {
                    Cext[(size_t)row * 1024 + col] = v + bias[col];
                }
            }
}

// ---------------------------------------------------------------------------
// K3 fused: QK^T + softmax-over-heads + w output + PV + gating.
// CTA = (b, 16 i-rows), 512 threads, warp == head. j-tile = 32.
// Dynamic smem:
//   kv  : uint32[16][32][72]  per-head K / tanhV staging (two pads: K rows
//         stored with stride 68 (QK B-frags: 4r+c conflict-free), tanhV rows
//         with stride 72 (PV B-frags: 8c+r conflict-free))
//   ssh : uint32[16][16][52]  S / w tiles (pad 52: 20r+c conflict-free A-frags)
// ---------------------------------------------------------------------------
#define KV_WORDS_H 2304                 // 32*72
#define SSH_WORDS_H 832                 // 16*52
#define K3_SMEM ((16 * KV_WORDS_H + 16 * SSH_WORDS_H) * 4)

__global__ __launch_bounds__(512, 1)
void attn_fused_kernel(const float* __restrict__ rels,
                       const float* __restrict__ attn_mask,
                       const void* __restrict__ kpm,
                       const float* __restrict__ rels_bias,
                       float* __restrict__ d_out) {
    extern __shared__ uint32_t smemu[];
    uint32_t* kv  = smemu;                       // [h][...]
    uint32_t* ssh = smemu + 16 * KV_WORDS_H;     // [h][i(16)][52]
    __shared__ float sbias[4][16];

    const int tid = threadIdx.x;
    const int warp = tid >> 5, lane = tid & 31;  // warp == head, lane == jp
    const int b = blockIdx.y;
    const int i0 = blockIdx.x * 16;
    const int r = lane >> 2, c = lane & 3;

    if (tid < 64) sbias[tid >> 4][tid & 15] = rels_bias[tid];  // [r][h]
    const int kmode = g_kpm_mode;

    uint32_t* kvh = kv + warp * KV_WORDS_H;
    uint32_t kvh_sh = (uint32_t)__cvta_generic_to_shared(kvh);
    uint32_t* sshh = ssh + warp * SSH_WORDS_H;

    // ---- load Q fragments (tf32 bits, resident for the whole CTA) ----
    const uint32_t* Qb = reinterpret_cast<const uint32_t*>(g_Q)
                       + (((size_t)(b * 16 + warp) * 1024) + i0) * 64;
    uint32_t qa[8][4];
#pragma unroll
    for (int kt = 0; kt < 8; ++kt) {
        qa[kt][0] = Qb[(size_t)r * 64 + kt * 8 + c];
        qa[kt][1] = Qb[(size_t)(r + 8) * 64 + kt * 8 + c];
        qa[kt][2] = Qb[(size_t)r * 64 + kt * 8 + c + 4];
        qa[kt][3] = Qb[(size_t)(r + 8) * 64 + kt * 8 + c + 4];
    }

    float pv[8][4];
#pragma unroll
    for (int nt = 0; nt < 8; ++nt)
#pragma unroll
        for (int e = 0; e < 4; ++e) pv[nt][e] = 0.f;

    const int ip = warp;                         // i within tile (phase 1)
    const int i1 = i0 + ip;
    const size_t mbase = (size_t)b * 1048576u + (size_t)i1 * 1024u;
    const size_t wout0 = 4194304u;               // B*L*E

    const char* Ksrc  = reinterpret_cast<const char*>(g_Kb)
                      + ((size_t)(b * 16 + warp) * 1024) * 256;   // 64 f32 = 256B/row
    const char* TVsrc = reinterpret_cast<const char*>(g_TV)
                      + ((size_t)(b * 16 + warp) * 1024) * 256;

    for (int j0 = 0; j0 < 1024; j0 += 32) {
        __syncthreads();   // ssh reuse guard (prev PV reads done)

        // ---- stage K tile [32][64] with row stride 68 (warp-local) ----
#pragma unroll
        for (int t = 0; t < 16; ++t) {
            int chunk = t * 32 + lane;           // 512 chunks of 16B
            int jj = chunk >> 4, q4 = chunk & 15;
            cp_async16(kvh_sh + (uint32_t)(jj * 68 + q4 * 4) * 4,
                       Ksrc + (size_t)(j0 + jj) * 256 + q4 * 16);
        }
        cp_async_commit();
        cp_async_wait0();
        __syncwarp();

        // ---- QK^T mma: S[16][32] = Q[16][64] * K[32][64]^T ----
        float sacc[4][4];
#pragma unroll
        for (int nt = 0; nt < 4; ++nt)
#pragma unroll
            for (int e = 0; e < 4; ++e) sacc[nt][e] = 0.f;
#pragma unroll
        for (int kt = 0; kt < 8; ++kt)
#pragma unroll
            for (int nt = 0; nt < 4; ++nt) {
                uint32_t bf[2];
                bf[0] = kvh[(nt * 8 + r) * 68 + kt * 8 + c];
                bf[1] = kvh[(nt * 8 + r) * 68 + kt * 8 + c + 4];
                mma_tf32(sacc[nt], qa[kt], bf);
            }
        // store S (f32) to ssh, pairs -> STS.64
#pragma unroll
        for (int nt = 0; nt < 4; ++nt) {
#pragma unroll
            for (int half = 0; half < 2; ++half) {
                int row = r + half * 8;
                float2 v2;
                v2.x = sacc[nt][half * 2 + 0];
                v2.y = sacc[nt][half * 2 + 1];
                *reinterpret_cast<float2*>(sshh + row * 52 + nt * 8 + 2 * c) = v2;
            }
        }
        __syncthreads();

        // ---- prefetch tanh(V) tile (row stride 72) while doing phase 1 ----
#pragma unroll
        for (int t = 0; t < 16; ++t) {
            int chunk = t * 32 + lane;
            int jj = chunk >> 4, q4 = chunk & 15;
            cp_async16(kvh_sh + (uint32_t)(jj * 72 + q4 * 4) * 4,
                       TVsrc + (size_t)(j0 + jj) * 256 + q4 * 16);
        }
        cp_async_commit();

        // ---- phase 1: softmax over heads at (i=ip, j=j0+lane) ----
        {
            const int j = j0 + lane;
            float s[16];
#pragma unroll
            for (int h = 0; h < 16; ++h)
                s[h] = __uint_as_float(ssh[h * SSH_WORDS_H + ip * 52 + lane]);
            const float4 rv = *reinterpret_cast<const float4*>(rels + (mbase + j) * 4);
            const float am = attn_mask[mbase + j];
            bool keep;
            if (kmode == 1)
                keep = reinterpret_cast<const unsigned char*>(kpm)[mbase + j] != 0;
            else if (kmode == 2)
                keep = reinterpret_cast<const unsigned short*>(kpm)[mbase + j] != 0;
            else
                keep = reinterpret_cast<const unsigned int*>(kpm)[mbase + j] != 0u;

            float mx = -1e30f;
#pragma unroll
            for (int h = 0; h < 16; ++h) {
                s[h] = (s[h] + rv.x * sbias[0][h] + rv.y * sbias[1][h]
                             + rv.z * sbias[2][h] + rv.w * sbias[3][h]) * 0.125f;
                mx = fmaxf(mx, s[h]);
            }
            float sum = 0.f;
#pragma unroll
            for (int h = 0; h < 16; ++h) { s[h] = __expf(s[h] - mx); sum += s[h]; }
            const float scale = keep ? (__expf(am) / sum) : 0.f;
#pragma unroll
            for (int h = 0; h < 16; ++h) {
                s[h] *= scale;
                ssh[h * SSH_WORDS_H + ip * 52 + lane] = f2tf(s[h]);
            }
            float* wp = d_out + wout0 + (mbase + j) * 16;
#pragma unroll
            for (int h4 = 0; h4 < 4; ++h4) {
                float4 wv;
                wv.x = s[h4 * 4 + 0]; wv.y = s[h4 * 4 + 1];
                wv.z = s[h4 * 4 + 2]; wv.w = s[h4 * 4 + 3];
                reinterpret_cast<float4*>(wp)[h4] = wv;
            }
        }
        cp_async_wait0();
        __syncwarp();      // tanhV staged (warp-local)
        __syncthreads();   // ssh w-tf32 visible to all warps

        // ---- PV mma: out[16][64] += w[16][32] * tanhV[32][64] ----
#pragma unroll
        for (int kt = 0; kt < 4; ++kt) {
            uint32_t af[4];
            af[0] = sshh[r * 52 + kt * 8 + c];
            af[1] = sshh[(r + 8) * 52 + kt * 8 + c];
            af[2] = sshh[r * 52 + kt * 8 + c + 4];
            af[3] = sshh[(r + 8) * 52 + kt * 8 + c + 4];
#pragma unroll
            for (int nt = 0; nt < 8; ++nt) {
                uint32_t bf[2];
                bf[0] = kvh[(kt * 8 + c) * 72 + nt * 8 + r];
                bf[1] = kvh[(kt * 8 + c + 4) * 72 + nt * 8 + r];
                mma_tf32(pv[nt], af, bf);
            }
        }
    }

    // ---- epilogue: gate with sigmoid(g), store for final projection ----
#pragma unroll
    for (int nt = 0; nt < 8; ++nt) {
        size_t base0 = ((size_t)(b * 1024 + i0 + r)) * 1024
                     + warp * 64 + nt * 8 + 2 * c;
        float2 sg0 = *reinterpret_cast<const float2*>(g_SG + base0);
        float2 o0;
        o0.x = pv[nt][0] * sg0.x;
        o0.y = pv[nt][1] * sg0.y;
        *reinterpret_cast<float2*>(g_gated + base0) = o0;
        size_t base1 = base0 + 8 * 1024;
        float2 sg1 = *reinterpret_cast<const float2*>(g_SG + base1);
        float2 o1;
        o1.x = pv[nt][2] * sg1.x;
        o1.y = pv[nt][3] * sg1.y;
        *reinterpret_cast<float2*>(g_gated + base1) = o1;
    }
}

// ---------------------------------------------------------------------------
// launch
// ---------------------------------------------------------------------------
extern "C" void kernel_launch(void* const* d_in, const int* in_sizes, int n_in,
                              void* d_out, int out_size) {
    (void)in_sizes; (void)n_in; (void)out_size;
    const float* query     = (const float*)d_in[0];
    const float* rels      = (const float*)d_in[1];
    const float* attn_mask = (const float*)d_in[2];
    const void*  kpm       = d_in[3];
    const float* proj_w    = (const float*)d_in[4];
    const float* proj_b    = (const float*)d_in[5];
    const float* out_w     = (const float*)d_in[6];
    const float* out_b     = (const float*)d_in[7];
    const float* rels_bias = (const float*)d_in[8];
    float* out = (float*)d_out;

    static bool attr_done = false;
    if (!attr_done) {
        cudaFuncSetAttribute(attn_fused_kernel,
                             cudaFuncAttributeMaxDynamicSharedMemorySize, K3_SMEM);
        attr_done = true;
    }

    detect_kpm_kernel<<<1, 256>>>((const unsigned int*)kpm);
    gemm_tf32_kernel<<<dim3(32, 32, 1), 256>>>(0, query, proj_w, proj_b, nullptr);
    attn_fused_kernel<<<dim3(64, 4, 1), 512, K3_SMEM>>>(rels, attn_mask, kpm, rels_bias, out);
    gemm_tf32_kernel<<<dim3(8, 32, 1), 256>>>(2, nullptr, out_w, out_b, out);
}

// round 10
// speedup vs baseline: 1.1824x; 1.1824x over previous
#include <cuda_runtime.h>
#include <cstdint>
#include <math.h>

// Problem constants
//  B=4, L=1024, E=1024, H=16, D=64, HID=1024, R=4
//  output: concat(out [4,1024,1024], w [4,1024,1024,16]) as float32

// ---------------------------------------------------------------------------
// Scratch (static device arrays; no allocations allowed)
// ---------------------------------------------------------------------------
__device__ float g_Q[4u * 16u * 1024u * 64u];      // [b][h][i][d]
__device__ float g_Kb[4u * 16u * 1024u * 64u];     // [b][h][j][d]
__device__ float g_TV[4u * 16u * 1024u * 64u];     // tanh(v)  [b][h][j][d]
__device__ float g_SG[4u * 1024u * 16u * 64u];     // sigmoid(g) [b][i][h*64+d]
__device__ float g_gated[4u * 1024u * 1024u];      // [b][i][hd]
__device__ float g_S[67108864u];                   // scores [b][h][i][j] (256MB)
__device__ int   g_kpm_mode;                       // 0=32-bit word, 1=u8, 2=u16

// ---------------------------------------------------------------------------
// Helpers
// ---------------------------------------------------------------------------
__device__ __forceinline__ uint32_t f2tf(float x) {
    uint32_t r;
    asm("cvt.rna.tf32.f32 %0, %1;" : "=r"(r) : "f"(x));
    return r;
}

__device__ __forceinline__ void mma_tf32(float (&d)[4], const uint32_t (&a)[4],
                                         const uint32_t (&b)[2]) {
    asm volatile(
        "mma.sync.aligned.m16n8k8.row.col.f32.tf32.tf32.f32 "
        "{%0,%1,%2,%3}, {%4,%5,%6,%7}, {%8,%9}, {%0,%1,%2,%3};\n"
        : "+f"(d[0]), "+f"(d[1]), "+f"(d[2]), "+f"(d[3])
        : "r"(a[0]), "r"(a[1]), "r"(a[2]), "r"(a[3]), "r"(b[0]), "r"(b[1]));
}

__device__ __forceinline__ void cp_async16(uint32_t dst_smem, const void* src) {
    asm volatile("cp.async.cg.shared.global [%0], [%1], 16;\n"
                 :: "r"(dst_smem), "l"(src));
}
__device__ __forceinline__ void cp_async_commit() {
    asm volatile("cp.async.commit_group;\n" ::: "memory");
}
__device__ __forceinline__ void cp_async_wait0() {
    asm volatile("cp.async.wait_group 0;\n" ::: "memory");
}
__device__ __forceinline__ void cp_async_wait1() {
    asm volatile("cp.async.wait_group 1;\n" ::: "memory");
}

// ---------------------------------------------------------------------------
// key_padding_mask dtype probe
// ---------------------------------------------------------------------------
__global__ void detect_kpm_kernel(const unsigned int* __restrict__ kpm) {
    __shared__ int s_f32, s_bf16, s_u8;
    if (threadIdx.x == 0) { s_f32 = 0; s_bf16 = 0; s_u8 = 0; }
    __syncthreads();
    for (int i = threadIdx.x; i < 1024; i += blockDim.x) {
        unsigned int w = kpm[i];
        if (w == 0x3F800000u) atomicOr(&s_f32, 1);
        else if ((w & 0xFFFFu) == 0x3F80u || (w >> 16) == 0x3F80u) atomicOr(&s_bf16, 1);
        else if (w > 1u) atomicOr(&s_u8, 1);
    }
    __syncthreads();
    if (threadIdx.x == 0) {
        int mode = 0;
        if (s_bf16) mode = 2;
        else if (s_f32) mode = 0;
        else if (s_u8) mode = 1;
        g_kpm_mode = mode;
    }
}

// ---------------------------------------------------------------------------
// tf32 GEMM v2: C[m,n] = sum_k A[m,k]*B[n,k], 128x128x32 tiles,
// cp.async double-buffered, f2tf at fragment load, 2 CTAs/SM.
//   mode 0: A=query, B=proj_w, epilogue splits QKVG
//   mode 1: batched z=b*16+h: A=g_Q[z], B=g_Kb[z], K=64, C=g_S[z]
//   mode 2: A=g_gated, B=out_w, C=d_out + out_b
// Dynamic smem: As[2][128][36] f32, Bs[2][128][36] f32 = 73728 B
// ---------------------------------------------------------------------------
#define GEMM_SMEM (2 * 2 * 128 * 36 * 4)

__global__ __launch_bounds__(256, 2)
void gemm_tf32_kernel(int mode, const float* __restrict__ Aext,
                      const float* __restrict__ Bext,
                      const float* __restrict__ bias, float* __restrict__ Cext) {
    extern __shared__ float gsm[];
    float* As = gsm;                       // [2][128][36]
    float* Bs = gsm + 2 * 128 * 36;        // [2][128][36]

    const int tid = threadIdx.x;
    const int warp = tid >> 5, lane = tid & 31;
    const int wm = warp >> 1, wn = warp & 1;
    const int r = lane >> 2, c = lane & 3;

    const float* Ap; const float* Bp; int lda, ldb, Kd;
    if (mode == 1) {
        size_t off = (size_t)blockIdx.z * 65536u;
        Ap = g_Q + off; Bp = g_Kb + off; lda = 64; ldb = 64; Kd = 64;
    } else if (mode == 2) {
        Ap = g_gated; Bp = Bext; lda = 1024; ldb = 1024; Kd = 1024;
    } else {
        Ap = Aext; Bp = Bext; lda = 1024; ldb = 1024; Kd = 1024;
    }
    const int m0 = blockIdx.y * 128;
    const int n0 = blockIdx.x * 128;

    float acc[2][8][4];
#pragma unroll
    for (int mt = 0; mt < 2; ++mt)
#pragma unroll
        for (int nt = 0; nt < 8; ++nt)
#pragma unroll
            for (int e = 0; e < 4; ++e) acc[mt][nt][e] = 0.f;

    const uint32_t sA = (uint32_t)__cvta_generic_to_shared(As);
    const uint32_t sB = (uint32_t)__cvta_generic_to_shared(Bs);

    auto load_stage = [&](int kb, int st) {
        const uint32_t baseA = sA + (uint32_t)st * (128 * 36 * 4);
        const uint32_t baseB = sB + (uint32_t)st * (128 * 36 * 4);
        const float* ga = Ap + kb * 32;
        const float* gb = Bp + kb * 32;
#pragma unroll
        for (int t = 0; t < 4; ++t) {
            int chunk = t * 256 + tid;           // 1024 16B chunks per array
            int row = chunk >> 3, c4 = chunk & 7;
            uint32_t off = (uint32_t)(row * 36 + c4 * 4) * 4;
            cp_async16(baseA + off, ga + (size_t)(m0 + row) * lda + c4 * 4);
            cp_async16(baseB + off, gb + (size_t)(n0 + row) * ldb + c4 * 4);
        }
        cp_async_commit();
    };

    auto compute = [&](int st) {
        const float* Ab = As + st * (128 * 36);
        const float* Bb = Bs + st * (128 * 36);
#pragma unroll
        for (int ks = 0; ks < 4; ++ks) {
            const int kk = ks * 8;
            uint32_t af[2][4], bf[8][2];
#pragma unroll
            for (int mt = 0; mt < 2; ++mt) {
                int row0 = wm * 32 + mt * 16 + r;
                af[mt][0] = f2tf(Ab[row0 * 36 + kk + c]);
                af[mt][1] = f2tf(Ab[(row0 + 8) * 36 + kk + c]);
                af[mt][2] = f2tf(Ab[row0 * 36 + kk + c + 4]);
                af[mt][3] = f2tf(Ab[(row0 + 8) * 36 + kk + c + 4]);
            }
#pragma unroll
            for (int nt = 0; nt < 8; ++nt) {
                int col0 = wn * 64 + nt * 8 + r;
                bf[nt][0] = f2tf(Bb[col0 * 36 + kk + c]);
                bf[nt][1] = f2tf(Bb[col0 * 36 + kk + c + 4]);
            }
#pragma unroll
            for (int mt = 0; mt < 2; ++mt)
#pragma unroll
                for (int nt = 0; nt < 8; ++nt)
                    mma_tf32(acc[mt][nt], af[mt], bf[nt]);
        }
    };

    const int nk = Kd >> 5;
    load_stage(0, 0);
    if (nk > 1) load_stage(1, 1);
    for (int kb = 0; kb < nk; ++kb) {
        if (kb + 1 < nk) cp_async_wait1(); else cp_async_wait0();
        __syncthreads();
        compute(kb & 1);
        __syncthreads();
        if (kb + 2 < nk) load_stage(kb + 2, kb & 1);
    }

    // epilogue
#pragma unroll
    for (int mt = 0; mt < 2; ++mt)
#pragma unroll
        for (int nt = 0; nt < 8; ++nt)
#pragma unroll
            for (int e = 0; e < 4; ++e) {
                int row = m0 + wm * 32 + mt * 16 + r + ((e >> 1) << 3);
                int col = n0 + wn * 64 + nt * 8 + 2 * c + (e & 1);
                float v = acc[mt][nt][e];
                if (mode == 0) {
                    v += bias[col];
                    int sec = col >> 10, cc = col & 1023;
                    int h = cc >> 6, d = cc & 63;
                    int b = row >> 10, i = row & 1023;
                    size_t hidx = (((size_t)b * 16 + h) * 1024 + i) * 64 + d;
                    if (sec == 0) g_Q[hidx] = v;
                    else if (sec == 1) g_Kb[hidx] = v;
                    else if (sec == 2) g_TV[hidx] = tanhf(v);
                    else g_SG[((size_t)(b * 1024 + i) * 16 + h) * 64 + d] =
                             1.0f / (1.0f + __expf(-v));
                } else if (mode == 1) {
                    g_S[(size_t)blockIdx.z * 1048576u + (size_t)row * 1024 + col] = v;
                } else {
                    Cext[(size_t)row * 1024 + col] = v + bias[col];
                }
            }
}

// ---------------------------------------------------------------------------
// K3: softmax over heads + w output + tensor-core PV + gating (R5 version)
// CTA = (b, 32 i-rows), 512 threads, 16 warps == 16 heads.
//   wsh : uint32[16][32][20]  (tf32 w, A-fragment layout, pad 20)
//   tvsh: uint32[16][16][72]  (tf32 tanhV tile per head, pad 72)
// ---------------------------------------------------------------------------
#define WSH_SZ  (16 * 32 * 20)
#define TVSH_SZ (16 * 16 * 72)
#define K3_SMEM ((WSH_SZ + TVSH_SZ) * 4)

__global__ __launch_bounds__(512, 1)
void attn_wpv_kernel(const float* __restrict__ rels,
                     const float* __restrict__ attn_mask,
                     const void* __restrict__ kpm,
                     const float* __restrict__ rels_bias,
                     float* __restrict__ d_out) {
    extern __shared__ uint32_t smemu[];
    uint32_t* wsh  = smemu;            // [h][i(32)][20], j in [0,16)
    uint32_t* tvsh = smemu + WSH_SZ;   // [h][j(16)][72], d in [0,64)
    __shared__ float sbias[4][16];

    const int tid = threadIdx.x;
    const int warp = tid >> 5, lane = tid & 31;
    const int b = blockIdx.y;
    const int i0 = blockIdx.x * 32;
    const int r = lane >> 2, c = lane & 3;

    if (tid < 64) sbias[tid >> 4][tid & 15] = rels_bias[tid];  // [r][h]
    const int kmode = g_kpm_mode;

    float acc[2][8][4];
#pragma unroll
    for (int mt = 0; mt < 2; ++mt)
#pragma unroll
        for (int nt = 0; nt < 8; ++nt)
#pragma unroll
            for (int e = 0; e < 4; ++e) acc[mt][nt][e] = 0.f;

    const int ip = tid >> 4;   // 0..31 : i within tile (phase 1)
    const int jp = tid & 15;   // 0..15 : j within tile (phase 1)
    const int i1 = i0 + ip;
    const size_t sbase0 = (size_t)b * 16777216u + (size_t)i1 * 1024u;  // S
    const size_t mbase  = (size_t)b * 1048576u + (size_t)i1 * 1024u;   // masks
    const size_t wout0  = 4194304u;                                    // B*L*E

    const float* tvb = g_TV + (size_t)(b * 16 + warp) * 65536u;
    uint32_t* tsh = tvsh + warp * (16 * 72);
    const uint32_t* wh = wsh + warp * (32 * 20);

    for (int j0 = 0; j0 < 1024; j0 += 16) {
        __syncthreads();   // wsh reuse guard
        // ---- phase 1: softmax over heads, write w (global + smem tf32) ----
        {
            const int j = j0 + jp;
            float s[16];
            const size_t sb = sbase0 + j;
#pragma unroll
            for (int h = 0; h < 16; ++h) s[h] = g_S[sb + (size_t)h * 1048576u];
            const float4 rv = *reinterpret_cast<const float4*>(rels + (mbase + j) * 4);
            const float am = attn_mask[mbase + j];
            bool keep;
            if (kmode == 1)
                keep = reinterpret_cast<const unsigned char*>(kpm)[mbase + j] != 0;
            else if (kmode == 2)
                keep = reinterpret_cast<const unsigned short*>(kpm)[mbase + j] != 0;
            else
                keep = reinterpret_cast<const unsigned int*>(kpm)[mbase + j] != 0u;

            float mx = -1e30f;
#pragma unroll
            for (int h = 0; h < 16; ++h) {
                s[h] = (s[h] + rv.x * sbias[0][h] + rv.y * sbias[1][h]
                             + rv.z * sbias[2][h] + rv.w * sbias[3][h]) * 0.125f;
                mx = fmaxf(mx, s[h]);
            }
            float sum = 0.f;
#pragma unroll
            for (int h = 0; h < 16; ++h) { s[h] = __expf(s[h] - mx); sum += s[h]; }
            const float scale = keep ? (__expf(am) / sum) : 0.f;
#pragma unroll
            for (int h = 0; h < 16; ++h) {
                s[h] *= scale;
                wsh[h * (32 * 20) + ip * 20 + jp] = f2tf(s[h]);
            }
            float* wp = d_out + wout0 + (mbase + j) * 16;
#pragma unroll
            for (int h4 = 0; h4 < 4; ++h4) {
                float4 wv;
                wv.x = s[h4 * 4 + 0]; wv.y = s[h4 * 4 + 1];
                wv.z = s[h4 * 4 + 2]; wv.w = s[h4 * 4 + 3];
                reinterpret_cast<float4*>(wp)[h4] = wv;
            }
        }
        __syncthreads();
        // ---- phase 2: tensor-core PV (warp == head) ----
        {
            const float* tv = tvb + (size_t)j0 * 64;
#pragma unroll
            for (int it = 0; it < 8; ++it) {
                int jj = it * 2 + (lane >> 4);
                int dd = (lane & 15) * 4;
                float4 t = *reinterpret_cast<const float4*>(tv + jj * 64 + dd);
                uint32_t* p = tsh + jj * 72 + dd;
                p[0] = f2tf(t.x); p[1] = f2tf(t.y);
                p[2] = f2tf(t.z); p[3] = f2tf(t.w);
            }
            __syncwarp();

            uint32_t af[2][2][4];
#pragma unroll
            for (int mt = 0; mt < 2; ++mt)
#pragma unroll
                for (int kt = 0; kt < 2; ++kt) {
                    const uint32_t* base = wh + (mt * 16 + r) * 20 + kt * 8 + c;
                    af[mt][kt][0] = base[0];
                    af[mt][kt][1] = base[8 * 20];
                    af[mt][kt][2] = base[4];
                    af[mt][kt][3] = base[8 * 20 + 4];
                }
#pragma unroll
            for (int kt = 0; kt < 2; ++kt)
#pragma unroll
                for (int nt = 0; nt < 8; ++nt) {
                    uint32_t bf[2];
                    bf[0] = tsh[(kt * 8 + c) * 72 + nt * 8 + r];
                    bf[1] = tsh[(kt * 8 + c + 4) * 72 + nt * 8 + r];
#pragma unroll
                    for (int mt = 0; mt < 2; ++mt)
                        mma_tf32(acc[mt][nt], af[mt][kt], bf);
                }
            __syncwarp();
        }
    }

    // ---- epilogue: gate with sigmoid(g), store for final projection ----
#pragma unroll
    for (int mt = 0; mt < 2; ++mt)
#pragma unroll
        for (int nt = 0; nt < 8; ++nt) {
            size_t base0 = ((size_t)(b * 1024 + i0 + mt * 16 + r)) * 1024
                         + warp * 64 + nt * 8 + 2 * c;
            float2 sg0 = *reinterpret_cast<const float2*>(g_SG + base0);
            float2 o0;
            o0.x = acc[mt][nt][0] * sg0.x;
            o0.y = acc[mt][nt][1] * sg0.y;
            *reinterpret_cast<float2*>(g_gated + base0) = o0;
            size_t base1 = base0 + 8 * 1024;
            float2 sg1 = *reinterpret_cast<const float2*>(g_SG + base1);
            float2 o1;
            o1.x = acc[mt][nt][2] * sg1.x;
            o1.y = acc[mt][nt][3] * sg1.y;
            *reinterpret_cast<float2*>(g_gated + base1) = o1;
        }
}

// ---------------------------------------------------------------------------
// launch
// ---------------------------------------------------------------------------
extern "C" void kernel_launch(void* const* d_in, const int* in_sizes, int n_in,
                              void* d_out, int out_size) {
    (void)in_sizes; (void)n_in; (void)out_size;
    const float* query     = (const float*)d_in[0];
    const float* rels      = (const float*)d_in[1];
    const float* attn_mask = (const float*)d_in[2];
    const void*  kpm       = d_in[3];
    const float* proj_w    = (const float*)d_in[4];
    const float* proj_b    = (const float*)d_in[5];
    const float* out_w     = (const float*)d_in[6];
    const float* out_b     = (const float*)d_in[7];
    const float* rels_bias = (const float*)d_in[8];
    float* out = (float*)d_out;

    static bool attr_done = false;
    if (!attr_done) {
        cudaFuncSetAttribute(attn_wpv_kernel,
                             cudaFuncAttributeMaxDynamicSharedMemorySize, K3_SMEM);
        cudaFuncSetAttribute(gemm_tf32_kernel,
                             cudaFuncAttributeMaxDynamicSharedMemorySize, GEMM_SMEM);
        attr_done = true;
    }

    detect_kpm_kernel<<<1, 256>>>((const unsigned int*)kpm);
    gemm_tf32_kernel<<<dim3(32, 32, 1), 256, GEMM_SMEM>>>(0, query, proj_w, proj_b, nullptr);
    gemm_tf32_kernel<<<dim3(8, 8, 64), 256, GEMM_SMEM>>>(1, nullptr, nullptr, nullptr, nullptr);
    attn_wpv_kernel<<<dim3(32, 4, 1), 512, K3_SMEM>>>(rels, attn_mask, kpm, rels_bias, out);
    gemm_tf32_kernel<<<dim3(8, 32, 1), 256, GEMM_SMEM>>>(2, nullptr, out_w, out_b, out);
}

// round 11
// speedup vs baseline: 1.2054x; 1.0194x over previous
#include <cuda_runtime.h>
#include <cstdint>
#include <math.h>

// Problem constants
//  B=4, L=1024, E=1024, H=16, D=64, HID=1024, R=4
//  output: concat(out [4,1024,1024], w [4,1024,1024,16]) as float32

// ---------------------------------------------------------------------------
// Scratch (static device arrays; no allocations allowed)
// g_TV holds tf32-rounded bit patterns (consumed only by MMAs via cp.async).
// ---------------------------------------------------------------------------
__device__ float g_Q[4u * 16u * 1024u * 64u];      // [b][h][i][d]
__device__ float g_Kb[4u * 16u * 1024u * 64u];     // [b][h][j][d]
__device__ float g_TV[4u * 16u * 1024u * 64u];     // tanh(v) tf32 bits
__device__ float g_SG[4u * 1024u * 16u * 64u];     // sigmoid(g) [b][i][h*64+d]
__device__ float g_gated[4u * 1024u * 1024u];      // [b][i][hd]
__device__ float g_S[67108864u];                   // scores [b][h][i][j] (256MB)
__device__ int   g_kpm_mode;                       // 0=32-bit word, 1=u8, 2=u16

// ---------------------------------------------------------------------------
// Helpers
// ---------------------------------------------------------------------------
__device__ __forceinline__ uint32_t f2tf(float x) {
    uint32_t r;
    asm("cvt.rna.tf32.f32 %0, %1;" : "=r"(r) : "f"(x));
    return r;
}
__device__ __forceinline__ float ex2(float x) {
    float y;
    asm("ex2.approx.f32 %0, %1;" : "=f"(y) : "f"(x));
    return y;
}

__device__ __forceinline__ void mma_tf32(float (&d)[4], const uint32_t (&a)[4],
                                         const uint32_t (&b)[2]) {
    asm volatile(
        "mma.sync.aligned.m16n8k8.row.col.f32.tf32.tf32.f32 "
        "{%0,%1,%2,%3}, {%4,%5,%6,%7}, {%8,%9}, {%0,%1,%2,%3};\n"
        : "+f"(d[0]), "+f"(d[1]), "+f"(d[2]), "+f"(d[3])
        : "r"(a[0]), "r"(a[1]), "r"(a[2]), "r"(a[3]), "r"(b[0]), "r"(b[1]));
}

__device__ __forceinline__ void cp_async16(uint32_t dst_smem, const void* src) {
    asm volatile("cp.async.cg.shared.global [%0], [%1], 16;\n"
                 :: "r"(dst_smem), "l"(src));
}
__device__ __forceinline__ void cp_async_commit() {
    asm volatile("cp.async.commit_group;\n" ::: "memory");
}
__device__ __forceinline__ void cp_async_wait0() {
    asm volatile("cp.async.wait_group 0;\n" ::: "memory");
}
__device__ __forceinline__ void cp_async_wait1() {
    asm volatile("cp.async.wait_group 1;\n" ::: "memory");
}
__device__ __forceinline__ void cp_async_wait2() {
    asm volatile("cp.async.wait_group 2;\n" ::: "memory");
}

// ---------------------------------------------------------------------------
// key_padding_mask dtype probe
// ---------------------------------------------------------------------------
__global__ void detect_kpm_kernel(const unsigned int* __restrict__ kpm) {
    __shared__ int s_f32, s_bf16, s_u8;
    if (threadIdx.x == 0) { s_f32 = 0; s_bf16 = 0; s_u8 = 0; }
    __syncthreads();
    for (int i = threadIdx.x; i < 1024; i += blockDim.x) {
        unsigned int w = kpm[i];
        if (w == 0x3F800000u) atomicOr(&s_f32, 1);
        else if ((w & 0xFFFFu) == 0x3F80u || (w >> 16) == 0x3F80u) atomicOr(&s_bf16, 1);
        else if (w > 1u) atomicOr(&s_u8, 1);
    }
    __syncthreads();
    if (threadIdx.x == 0) {
        int mode = 0;
        if (s_bf16) mode = 2;
        else if (s_f32) mode = 0;
        else if (s_u8) mode = 1;
        g_kpm_mode = mode;
    }
}

// ---------------------------------------------------------------------------
// tf32 GEMM v2 (unchanged from R9 winner, except g_TV stores tf32 bits)
// ---------------------------------------------------------------------------
#define GEMM_SMEM (2 * 2 * 128 * 36 * 4)

__global__ __launch_bounds__(256, 2)
void gemm_tf32_kernel(int mode, const float* __restrict__ Aext,
                      const float* __restrict__ Bext,
                      const float* __restrict__ bias, float* __restrict__ Cext) {
    extern __shared__ float gsm[];
    float* As = gsm;                       // [2][128][36]
    float* Bs = gsm + 2 * 128 * 36;        // [2][128][36]

    const int tid = threadIdx.x;
    const int warp = tid >> 5, lane = tid & 31;
    const int wm = warp >> 1, wn = warp & 1;
    const int r = lane >> 2, c = lane & 3;

    const float* Ap; const float* Bp; int lda, ldb, Kd;
    if (mode == 1) {
        size_t off = (size_t)blockIdx.z * 65536u;
        Ap = g_Q + off; Bp = g_Kb + off; lda = 64; ldb = 64; Kd = 64;
    } else if (mode == 2) {
        Ap = g_gated; Bp = Bext; lda = 1024; ldb = 1024; Kd = 1024;
    } else {
        Ap = Aext; Bp = Bext; lda = 1024; ldb = 1024; Kd = 1024;
    }
    const int m0 = blockIdx.y * 128;
    const int n0 = blockIdx.x * 128;

    float acc[2][8][4];
#pragma unroll
    for (int mt = 0; mt < 2; ++mt)
#pragma unroll
        for (int nt = 0; nt < 8; ++nt)
#pragma unroll
            for (int e = 0; e < 4; ++e) acc[mt][nt][e] = 0.f;

    const uint32_t sA = (uint32_t)__cvta_generic_to_shared(As);
    const uint32_t sB = (uint32_t)__cvta_generic_to_shared(Bs);

    auto load_stage = [&](int kb, int st) {
        const uint32_t baseA = sA + (uint32_t)st * (128 * 36 * 4);
        const uint32_t baseB = sB + (uint32_t)st * (128 * 36 * 4);
        const float* ga = Ap + kb * 32;
        const float* gb = Bp + kb * 32;
#pragma unroll
        for (int t = 0; t < 4; ++t) {
            int chunk = t * 256 + tid;
            int row = chunk >> 3, c4 = chunk & 7;
            uint32_t off = (uint32_t)(row * 36 + c4 * 4) * 4;
            cp_async16(baseA + off, ga + (size_t)(m0 + row) * lda + c4 * 4);
            cp_async16(baseB + off, gb + (size_t)(n0 + row) * ldb + c4 * 4);
        }
        cp_async_commit();
    };

    auto compute = [&](int st) {
        const float* Ab = As + st * (128 * 36);
        const float* Bb = Bs + st * (128 * 36);
#pragma unroll
        for (int ks = 0; ks < 4; ++ks) {
            const int kk = ks * 8;
            uint32_t af[2][4], bf[8][2];
#pragma unroll
            for (int mt = 0; mt < 2; ++mt) {
                int row0 = wm * 32 + mt * 16 + r;
                af[mt][0] = f2tf(Ab[row0 * 36 + kk + c]);
                af[mt][1] = f2tf(Ab[(row0 + 8) * 36 + kk + c]);
                af[mt][2] = f2tf(Ab[row0 * 36 + kk + c + 4]);
                af[mt][3] = f2tf(Ab[(row0 + 8) * 36 + kk + c + 4]);
            }
#pragma unroll
            for (int nt = 0; nt < 8; ++nt) {
                int col0 = wn * 64 + nt * 8 + r;
                bf[nt][0] = f2tf(Bb[col0 * 36 + kk + c]);
                bf[nt][1] = f2tf(Bb[col0 * 36 + kk + c + 4]);
            }
#pragma unroll
            for (int mt = 0; mt < 2; ++mt)
#pragma unroll
                for (int nt = 0; nt < 8; ++nt)
                    mma_tf32(acc[mt][nt], af[mt], bf[nt]);
        }
    };

    const int nk = Kd >> 5;
    load_stage(0, 0);
    if (nk > 1) load_stage(1, 1);
    for (int kb = 0; kb < nk; ++kb) {
        if (kb + 1 < nk) cp_async_wait1(); else cp_async_wait0();
        __syncthreads();
        compute(kb & 1);
        __syncthreads();
        if (kb + 2 < nk) load_stage(kb + 2, kb & 1);
    }

#pragma unroll
    for (int mt = 0; mt < 2; ++mt)
#pragma unroll
        for (int nt = 0; nt < 8; ++nt)
#pragma unroll
            for (int e = 0; e < 4; ++e) {
                int row = m0 + wm * 32 + mt * 16 + r + ((e >> 1) << 3);
                int col = n0 + wn * 64 + nt * 8 + 2 * c + (e & 1);
                float v = acc[mt][nt][e];
                if (mode == 0) {
                    v += bias[col];
                    int sec = col >> 10, cc = col & 1023;
                    int h = cc >> 6, d = cc & 63;
                    int b = row >> 10, i = row & 1023;
                    size_t hidx = (((size_t)b * 16 + h) * 1024 + i) * 64 + d;
                    if (sec == 0) g_Q[hidx] = v;
                    else if (sec == 1) g_Kb[hidx] = v;
                    else if (sec == 2) g_TV[hidx] = __uint_as_float(f2tf(tanhf(v)));
                    else g_SG[((size_t)(b * 1024 + i) * 16 + h) * 64 + d] =
                             1.0f / (1.0f + __expf(-v));
                } else if (mode == 1) {
                    g_S[(size_t)blockIdx.z * 1048576u + (size_t)row * 1024 + col] = v;
                } else {
                    Cext[(size_t)row * 1024 + col] = v + bias[col];
                }
            }
}

// ---------------------------------------------------------------------------
// K3 v3: fully cp.async-pipelined softmax-over-heads + w + tensor-core PV.
// CTA = (b, 32 i-rows), 512 threads, warp == head.
// smem (words):
//   wsh  [16][32][20]          w tf32 A-frags              (10240)
//   tvsh [16][16][72]          tanhV tf32 (cp.async)       (18432)
//   sst  [2][16][32*16]        S prefetch, idx h*512+tid   (16384)
//   rst  [2][512]*4            rels float4 prefetch        ( 4096)
//   mst  [2][512]              attn_mask prefetch          ( 1024)
// total 50176 words = 196 KB
// ---------------------------------------------------------------------------
#define WSH_SZ  (16 * 32 * 20)
#define TVSH_SZ (16 * 16 * 72)
#define SST_SZ  (2 * 16 * 512)
#define RST_SZ  (2 * 512 * 4)
#define MST_SZ  (2 * 512)
#define K3_SMEM ((WSH_SZ + TVSH_SZ + SST_SZ + RST_SZ + MST_SZ) * 4)

__global__ __launch_bounds__(512, 1)
void attn_wpv_kernel(const float* __restrict__ rels,
                     const float* __restrict__ attn_mask,
                     const void* __restrict__ kpm,
                     const float* __restrict__ rels_bias,
                     float* __restrict__ d_out) {
    extern __shared__ uint32_t smemu[];
    uint32_t* wsh  = smemu;                          // [h][i(32)][20]
    uint32_t* tvsh = smemu + WSH_SZ;                 // [h][j(16)][72]
    float*    sst  = (float*)(smemu + WSH_SZ + TVSH_SZ);          // [2][16][512]
    float*    rstf = sst + SST_SZ;                                // [2][512] f4
    float*    mst  = rstf + RST_SZ;                               // [2][512]
    __shared__ float sbias[4][16];

    const int tid = threadIdx.x;
    const int warp = tid >> 5, lane = tid & 31;
    const int b = blockIdx.y;
    const int i0 = blockIdx.x * 32;
    const int r = lane >> 2, c = lane & 3;

    // fold 1/sqrt(D) * log2(e) into the bias so exp == raw ex2
    const float CSC = 0.125f * 1.4426950408889634f;
    if (tid < 64) sbias[tid >> 4][tid & 15] = rels_bias[tid] * CSC;
    const int kmode = g_kpm_mode;

    float acc[2][8][4];
#pragma unroll
    for (int mt = 0; mt < 2; ++mt)
#pragma unroll
        for (int nt = 0; nt < 8; ++nt)
#pragma unroll
            for (int e = 0; e < 4; ++e) acc[mt][nt][e] = 0.f;

    const int ip = tid >> 4;   // i within tile
    const int jp = tid & 15;   // j within tile
    const int i1 = i0 + ip;
    const size_t mbase = (size_t)b * 1048576u + (size_t)i1 * 1024u;
    const size_t wout0 = 4194304u;

    const uint32_t sst_u32 = (uint32_t)__cvta_generic_to_shared(sst);
    const uint32_t rst_u32 = (uint32_t)__cvta_generic_to_shared(rstf);
    const uint32_t mst_u32 = (uint32_t)__cvta_generic_to_shared(mst);
    const uint32_t tv_u32  = (uint32_t)__cvta_generic_to_shared(tvsh);

    const float* Ssrc  = g_S + (size_t)b * 16777216u + (size_t)warp * 1048576u
                       + (size_t)i0 * 1024u;                 // + i*1024 + j
    const float* TVsrc = g_TV + (size_t)(b * 16 + warp) * 65536u;
    uint32_t* tsh = tvsh + warp * (16 * 72);
    const uint32_t* wh = wsh + warp * (32 * 20);

    // stage S(jn)+rels(jn)+mask(jn) into buffer bufn (no commit inside)
    auto stage_srm = [&](int jn, int bufn) {
        // S: warp == head, 32 rows x 64B
#pragma unroll
        for (int t2 = 0; t2 < 4; ++t2) {
            int chunk = t2 * 32 + lane;
            int i = chunk >> 2, c4 = chunk & 3;
            cp_async16(sst_u32 + (uint32_t)(bufn * 8192 + warp * 512 + i * 16 + c4 * 4) * 4,
                       Ssrc + (size_t)i * 1024 + jn + c4 * 4);
        }
        // rels: one float4 per thread
        cp_async16(rst_u32 + (uint32_t)(bufn * 2048 + tid * 4) * 4,
                   rels + (((size_t)(b * 1024 + i0 + (tid >> 4)) * 1024) + jn + (tid & 15)) * 4);
        // attn_mask: threads 0..127, 16B each
        if (tid < 128) {
            int i = tid >> 2, q = tid & 3;
            cp_async16(mst_u32 + (uint32_t)(bufn * 512 + i * 16 + q * 4) * 4,
                       attn_mask + (size_t)(b * 1024 + i0 + i) * 1024 + jn + q * 4);
        }
    };

    // prologue: group G0 = S/rels/mask for tile 0
    stage_srm(0, 0);
    cp_async_commit();

    for (int t = 0; t < 64; ++t) {
        const int j0 = t * 16;
        const int buf = t & 1;

        // group: TV(t) (warp-local tsh slice; prior phase-2 reads completed)
#pragma unroll
        for (int t2 = 0; t2 < 8; ++t2) {
            int chunk = t2 * 32 + lane;
            int jj = chunk >> 4, q4 = chunk & 15;
            cp_async16(tv_u32 + (uint32_t)(warp * 1152 + jj * 72 + q4 * 4) * 4,
                       TVsrc + (size_t)(j0 + jj) * 64 + q4 * 4);
        }
        cp_async_commit();

        // group: S/rels/mask for tile t+1 (empty group at t==63)
        if (t + 1 < 64) stage_srm(j0 + 16, buf ^ 1);
        cp_async_commit();

        cp_async_wait2();   // S(t)/rels(t)/mask(t) ready
        __syncthreads();    // + wsh free (previous phase 2 done)

        // ---- phase 1: softmax over heads at (i=ip, j=j0+jp) ----
        {
            const int j = j0 + jp;
            const float4 rv = reinterpret_cast<const float4*>(rstf)[buf * 512 + tid];
            const float am = mst[buf * 512 + tid];
            bool keep;
            if (kmode == 1)
                keep = reinterpret_cast<const unsigned char*>(kpm)[mbase + j] != 0;
            else if (kmode == 2)
                keep = reinterpret_cast<const unsigned short*>(kpm)[mbase + j] != 0;
            else
                keep = reinterpret_cast<const unsigned int*>(kpm)[mbase + j] != 0u;

            const float dot0 = rv.w * sbias[3][0];
            float u[16], mx = -1e30f;
#pragma unroll
            for (int h = 0; h < 16; ++h) {
                float d4 = fmaf(rv.x, sbias[0][h],
                           fmaf(rv.y, sbias[1][h],
                           fmaf(rv.z, sbias[2][h], rv.w * sbias[3][h])));
                u[h] = fmaf(sst[buf * 8192 + h * 512 + tid], CSC, d4);
                mx = fmaxf(mx, u[h]);
            }
            (void)dot0;
            float sum = 0.f;
#pragma unroll
            for (int h = 0; h < 16; ++h) { u[h] = ex2(u[h] - mx); sum += u[h]; }
            const float scale = keep ? __fdividef(__expf(am), sum) : 0.f;
#pragma unroll
            for (int h = 0; h < 16; ++h) {
                u[h] *= scale;
                wsh[h * (32 * 20) + ip * 20 + jp] = f2tf(u[h]);
            }
            float* wp = d_out + wout0 + (mbase + j) * 16;
#pragma unroll
            for (int h4 = 0; h4 < 4; ++h4) {
                float4 wv;
                wv.x = u[h4 * 4 + 0]; wv.y = u[h4 * 4 + 1];
                wv.z = u[h4 * 4 + 2]; wv.w = u[h4 * 4 + 3];
                reinterpret_cast<float4*>(wp)[h4] = wv;
            }
        }

        cp_async_wait1();   // TV(t) ready (S(t+1) may still be in flight)
        __syncthreads();    // wsh visible to all warps

        // ---- phase 2: PV MMA (warp == head) ----
        {
            uint32_t af[2][2][4];
#pragma unroll
            for (int mt = 0; mt < 2; ++mt)
#pragma unroll
                for (int kt = 0; kt < 2; ++kt) {
                    const uint32_t* base = wh + (mt * 16 + r) * 20 + kt * 8 + c;
                    af[mt][kt][0] = base[0];
                    af[mt][kt][1] = base[8 * 20];
                    af[mt][kt][2] = base[4];
                    af[mt][kt][3] = base[8 * 20 + 4];
                }
#pragma unroll
            for (int kt = 0; kt < 2; ++kt)
#pragma unroll
                for (int nt = 0; nt < 8; ++nt) {
                    uint32_t bf[2];
                    bf[0] = tsh[(kt * 8 + c) * 72 + nt * 8 + r];
                    bf[1] = tsh[(kt * 8 + c + 4) * 72 + nt * 8 + r];
#pragma unroll
                    for (int mt = 0; mt < 2; ++mt)
                        mma_tf32(acc[mt][nt], af[mt][kt], bf);
                }
        }
    }

    // ---- epilogue: gate with sigmoid(g), store for final projection ----
#pragma unroll
    for (int mt = 0; mt < 2; ++mt)
#pragma unroll
        for (int nt = 0; nt < 8; ++nt) {
            size_t base0 = ((size_t)(b * 1024 + i0 + mt * 16 + r)) * 1024
                         + warp * 64 + nt * 8 + 2 * c;
            float2 sg0 = *reinterpret_cast<const float2*>(g_SG + base0);
            float2 o0;
            o0.x = acc[mt][nt][0] * sg0.x;
            o0.y = acc[mt][nt][1] * sg0.y;
            *reinterpret_cast<float2*>(g_gated + base0) = o0;
            size_t base1 = base0 + 8 * 1024;
            float2 sg1 = *reinterpret_cast<const float2*>(g_SG + base1);
            float2 o1;
            o1.x = acc[mt][nt][2] * sg1.x;
            o1.y = acc[mt][nt][3] * sg1.y;
            *reinterpret_cast<float2*>(g_gated + base1) = o1;
        }
}

// ---------------------------------------------------------------------------
// launch
// ---------------------------------------------------------------------------
extern "C" void kernel_launch(void* const* d_in, const int* in_sizes, int n_in,
                              void* d_out, int out_size) {
    (void)in_sizes; (void)n_in; (void)out_size;
    const float* query     = (const float*)d_in[0];
    const float* rels      = (const float*)d_in[1];
    const float* attn_mask = (const float*)d_in[2];
    const void*  kpm       = d_in[3];
    const float* proj_w    = (const float*)d_in[4];
    const float* proj_b    = (const float*)d_in[5];
    const float* out_w     = (const float*)d_in[6];
    const float* out_b     = (const float*)d_in[7];
    const float* rels_bias = (const float*)d_in[8];
    float* out = (float*)d_out;

    static bool attr_done = false;
    if (!attr_done) {
        cudaFuncSetAttribute(attn_wpv_kernel,
                             cudaFuncAttributeMaxDynamicSharedMemorySize, K3_SMEM);
        cudaFuncSetAttribute(gemm_tf32_kernel,
                             cudaFuncAttributeMaxDynamicSharedMemorySize, GEMM_SMEM);
        attr_done = true;
    }

    detect_kpm_kernel<<<1, 256>>>((const unsigned int*)kpm);
    gemm_tf32_kernel<<<dim3(32, 32, 1), 256, GEMM_SMEM>>>(0, query, proj_w, proj_b, nullptr);
    gemm_tf32_kernel<<<dim3(8, 8, 64), 256, GEMM_SMEM>>>(1, nullptr, nullptr, nullptr, nullptr);
    attn_wpv_kernel<<<dim3(32, 4, 1), 512, K3_SMEM>>>(rels, attn_mask, kpm, rels_bias, out);
    gemm_tf32_kernel<<<dim3(8, 32, 1), 256, GEMM_SMEM>>>(2, nullptr, out_w, out_b, out);
}